// round 1
// baseline (speedup 1.0000x reference)
#include <cuda_runtime.h>

#define B_   16
#define T_   200
#define U1_  101
#define U_   100
#define V_   512
#define NEGV (-1e30f)

// Scratch: per-cell blank/emit log-probs and per-batch costs.
__device__ float g_blank[B_ * T_ * U1_];
__device__ float g_emit [B_ * T_ * U1_];
__device__ float g_cost [B_];

// ---------------------------------------------------------------------------
// Kernel 1: per-row log-softmax stats. One warp per (b,t,u) row of V=512.
// Each lane holds 16 floats (4 x float4), single pass over HBM.
// ---------------------------------------------------------------------------
__global__ void __launch_bounds__(256) rnnt_softmax_kernel(
    const float* __restrict__ acts,
    const int*   __restrict__ labels,
    const int*   __restrict__ label_lens)
{
    const int warp = (blockIdx.x * blockDim.x + threadIdx.x) >> 5;
    const int lane = threadIdx.x & 31;
    const int R = B_ * T_ * U1_;
    if (warp >= R) return;

    const int u = warp % U1_;
    const int b = warp / (T_ * U1_);

    const float4* __restrict__ p =
        reinterpret_cast<const float4*>(acts + (size_t)warp * V_);
    float4 v0 = p[lane];
    float4 v1 = p[lane + 32];
    float4 v2 = p[lane + 64];
    float4 v3 = p[lane + 96];

    // max reduce
    float m = fmaxf(fmaxf(fmaxf(v0.x, v0.y), fmaxf(v0.z, v0.w)),
                    fmaxf(fmaxf(v1.x, v1.y), fmaxf(v1.z, v1.w)));
    m = fmaxf(m, fmaxf(fmaxf(fmaxf(v2.x, v2.y), fmaxf(v2.z, v2.w)),
                       fmaxf(fmaxf(v3.x, v3.y), fmaxf(v3.z, v3.w))));
    #pragma unroll
    for (int off = 16; off > 0; off >>= 1)
        m = fmaxf(m, __shfl_xor_sync(0xffffffffu, m, off));

    // sum(exp(x - m)) reduce
    float s = __expf(v0.x - m) + __expf(v0.y - m) + __expf(v0.z - m) + __expf(v0.w - m)
            + __expf(v1.x - m) + __expf(v1.y - m) + __expf(v1.z - m) + __expf(v1.w - m)
            + __expf(v2.x - m) + __expf(v2.y - m) + __expf(v2.z - m) + __expf(v2.w - m)
            + __expf(v3.x - m) + __expf(v3.y - m) + __expf(v3.z - m) + __expf(v3.w - m);
    #pragma unroll
    for (int off = 16; off > 0; off >>= 1)
        s += __shfl_xor_sync(0xffffffffu, s, off);

    const float lse = m + __logf(s);

    // blank logit = element 0 (lane 0, v0.x)
    const float blank_logit = __shfl_sync(0xffffffffu, v0.x, 0);

    // label logit: uniform label index across the warp
    int lbl = 0;
    if (u < U_) lbl = labels[b * U_ + u];
    const int j   = lbl >> 2;
    const int src = j & 31;
    const int k   = j >> 5;
    const int c   = lbl & 3;
    float4 sel = (k == 0) ? v0 : (k == 1) ? v1 : (k == 2) ? v2 : v3;
    float cand = (c == 0) ? sel.x : (c == 1) ? sel.y : (c == 2) ? sel.z : sel.w;
    const float label_logit = __shfl_sync(0xffffffffu, cand, src);

    if (lane == 0) {
        const int llen = label_lens[b];
        g_blank[warp] = blank_logit - lse;
        g_emit [warp] = (u < llen) ? (label_logit - lse) : NEGV;
    }
}

// ---------------------------------------------------------------------------
// Kernel 2: forward DP per batch (anti-diagonal wavefront).
// alpha[t][u] = logaddexp(alpha[t-1][u] + blank[t-1][u],
//                         alpha[t][u-1] + emit[t][u-1])
// Both deps live on diagonal d-1 -> single previous-diagonal buffer.
// blank/emit for the whole batch staged in SMEM (2 * 80.8 KB).
// ---------------------------------------------------------------------------
__global__ void __launch_bounds__(128) rnnt_dp_kernel(
    const int* __restrict__ act_lens,
    const int* __restrict__ label_lens)
{
    extern __shared__ float sm[];
    float* blank_s = sm;               // T_*U1_
    float* emit_s  = sm + T_ * U1_;    // T_*U1_
    __shared__ float abuf[2][U1_];

    const int b   = blockIdx.x;
    const int tid = threadIdx.x;

    // Stage this batch's blank/emit into SMEM (coalesced float4).
    {
        const float4* gb = reinterpret_cast<const float4*>(g_blank + b * T_ * U1_);
        const float4* ge = reinterpret_cast<const float4*>(g_emit  + b * T_ * U1_);
        float4* sb = reinterpret_cast<float4*>(blank_s);
        float4* se = reinterpret_cast<float4*>(emit_s);
        const int N4 = (T_ * U1_) / 4;   // 5050
        for (int i = tid; i < N4; i += blockDim.x) {
            sb[i] = gb[i];
            se[i] = ge[i];
        }
    }

    const int alen  = act_lens[b];
    const int llen  = label_lens[b];
    const int dstar = (alen - 1) + llen;
    const int u     = tid;
    float saved = 0.0f;

    // d = 0: only cell (0,0) = 0, everything else on the diagonal invalid.
    if (u < U1_) abuf[0][u] = (u == 0) ? 0.0f : NEGV;
    __syncthreads();

    int cur = 0;
    for (int d = 1; d <= T_ + U1_ - 2; ++d) {
        const int nxt = cur ^ 1;
        if (u < U1_) {
            const int t = d - u;
            float v = NEGV;
            if (t >= 0 && t < T_) {
                const float top  = (t >= 1)
                    ? abuf[cur][u]     + blank_s[(t - 1) * U1_ + u]     : NEGV;
                const float left = (u >= 1)
                    ? abuf[cur][u - 1] + emit_s [ t      * U1_ + u - 1] : NEGV;
                const float mx = fmaxf(top, left);
                const float mn = fminf(top, left);
                v = mx + log1pf(__expf(mn - mx));
            }
            abuf[nxt][u] = v;
            if (d == dstar && u == llen) saved = v;
        }
        cur = nxt;
        __syncthreads();
    }

    if (u == llen)
        g_cost[b] = -(saved + blank_s[(alen - 1) * U1_ + llen]);
}

// ---------------------------------------------------------------------------
// Kernel 3: deterministic fixed-order reduction of the 16 costs.
// ---------------------------------------------------------------------------
__global__ void rnnt_finalize_kernel(float* __restrict__ out)
{
    if (threadIdx.x == 0 && blockIdx.x == 0) {
        float s = 0.0f;
        #pragma unroll
        for (int i = 0; i < B_; ++i) s += g_cost[i];
        out[0] = s / (float)B_;
    }
}

// ---------------------------------------------------------------------------
extern "C" void kernel_launch(void* const* d_in, const int* in_sizes, int n_in,
                              void* d_out, int out_size)
{
    const float* acts       = (const float*)d_in[0];
    const int*   labels     = (const int*)  d_in[1];
    const int*   act_lens   = (const int*)  d_in[2];
    const int*   label_lens = (const int*)  d_in[3];
    float*       out        = (float*)      d_out;

    const int rows   = B_ * T_ * U1_;          // 323,200 rows
    const int wpb    = 8;                      // warps per block
    const int blocks = (rows + wpb - 1) / wpb; // 40,400

    rnnt_softmax_kernel<<<blocks, wpb * 32>>>(acts, labels, label_lens);

    const size_t smemBytes = (size_t)2 * T_ * U1_ * sizeof(float);  // 161,600 B
    cudaFuncSetAttribute(rnnt_dp_kernel,
                         cudaFuncAttributeMaxDynamicSharedMemorySize,
                         (int)smemBytes);
    rnnt_dp_kernel<<<B_, 128, smemBytes>>>(act_lens, label_lens);

    rnnt_finalize_kernel<<<1, 32>>>(out);
}